// round 16
// baseline (speedup 1.0000x reference)
#include <cuda_runtime.h>
#include <cuda_fp16.h>
#include <cuda_bf16.h>
#include <stdint.h>

// Problem constants
#define NB   4        // batches
#define NQ   2048     // N_LC = N_TE
#define NP   2049     // NQ + dustbin
#define MD   256      // feature dim D
#define STR  2064     // padded stride for a/b vectors
#define NT   129      // 16x16 tiles per dim (129*16 = 2064, zero-padded)

// Persistent sink config: 148 blocks, 37/batch
#define NBLK 148
#define SUBB 37

// ---------------- device scratch (static, no allocation) ----------------
// K in mma A-fragment layout: [batch][row-tile][col-tile][lane] = 16 bytes
static __device__ uint4 g_Kp [(size_t)NB * NT * NT * 32];   // exp(Z) tiles
static __device__ uint4 g_KTp[(size_t)NB * NT * NT * 32];   // exp(Z)^T tiles
static __device__ float  g_f1[(size_t)NB * NQ * MD];
static __device__ float  g_f2[(size_t)NB * NQ * MD];
static __device__ float  g_h1[(size_t)NB * NQ * MD];
static __device__ float  g_h2[(size_t)NB * NQ * MD];
static __device__ __nv_bfloat16 g_s1h[(size_t)NB * NQ * MD];
static __device__ __nv_bfloat16 g_s1l[(size_t)NB * NQ * MD];
static __device__ __nv_bfloat16 g_s2h[(size_t)NB * NQ * MD];
static __device__ __nv_bfloat16 g_s2l[(size_t)NB * NQ * MD];
static __device__ float  g_a [NB * STR];                // scaled a' = 4096*a
static __device__ float  g_bv[NB * STR];                // b
// per-batch barrier state, each counter/epoch on its own 128B line
static __device__ unsigned g_bar_cnt[NB * 32];
static __device__ unsigned g_bar_epoch[NB * 32];
// per-batch, per-iteration "not converged" flags
static __device__ int g_conv[NB * 128];

// ---------------- MLP GEMM: 2 pointer sets selected by blockIdx.z ----------
struct MlpArgs {
    const float* A[2];
    const float* B[2];
    const float* bias[2];
    float* C[2];
};

__global__ __launch_bounds__(256, 2)
void sgemm_mlp(MlpArgs args, int relu)
{
    __shared__ float As[8][128];
    __shared__ float Bs[8][128];
    const int z = blockIdx.z;
    const float* A = args.A[z];
    const float* B = args.B[z];
    const float* bias = args.bias[z];
    float* C = args.C[z];
    const int K = MD;

    const int tid = threadIdx.x;
    const int tx = tid & 15, ty = tid >> 4;
    const int brow = blockIdx.y << 7;
    const int bcol = blockIdx.x << 7;
    const int lr = tid >> 1;
    const int lk = (tid & 1) << 2;

    const float* Ald = A + (long long)(brow + lr) * K + lk;
    const float* Bld = B + (long long)(bcol + lr) * K + lk;

    float acc[8][8];
#pragma unroll
    for (int i = 0; i < 8; i++)
#pragma unroll
        for (int j = 0; j < 8; j++) acc[i][j] = 0.f;

    for (int kk = 0; kk < K; kk += 8) {
        float4 av = *(const float4*)(Ald + kk);
        float4 bv = *(const float4*)(Bld + kk);
        __syncthreads();
        As[lk + 0][lr] = av.x; As[lk + 1][lr] = av.y;
        As[lk + 2][lr] = av.z; As[lk + 3][lr] = av.w;
        Bs[lk + 0][lr] = bv.x; Bs[lk + 1][lr] = bv.y;
        Bs[lk + 2][lr] = bv.z; Bs[lk + 3][lr] = bv.w;
        __syncthreads();
#pragma unroll
        for (int k = 0; k < 8; k++) {
            float ar[8], br[8];
            *(float4*)&ar[0] = *(const float4*)&As[k][ty * 4];
            *(float4*)&ar[4] = *(const float4*)&As[k][ty * 4 + 64];
            *(float4*)&br[0] = *(const float4*)&Bs[k][tx * 4];
            *(float4*)&br[4] = *(const float4*)&Bs[k][tx * 4 + 64];
#pragma unroll
            for (int i = 0; i < 8; i++)
#pragma unroll
                for (int j = 0; j < 8; j++)
                    acc[i][j] = fmaf(ar[i], br[j], acc[i][j]);
        }
    }

#pragma unroll
    for (int i = 0; i < 8; i++) {
        int row = brow + ty * 4 + ((i < 4) ? i : 60 + i);
#pragma unroll
        for (int j = 0; j < 8; j++) {
            int col = bcol + tx * 4 + ((j < 4) ? j : 60 + j);
            float v = acc[i][j] + bias[col];
            if (relu) v = fmaxf(v, 0.f);
            C[(long long)row * MD + col] = v;
        }
    }
}

// ---------------- split fp32 -> bf16 hi + lo ----------------
__global__ void split_bf16(const float* __restrict__ f1, const float* __restrict__ f2,
                           __nv_bfloat16* __restrict__ h1, __nv_bfloat16* __restrict__ l1,
                           __nv_bfloat16* __restrict__ h2, __nv_bfloat16* __restrict__ l2)
{
    int i = blockIdx.x * 256 + threadIdx.x;
    {
        float x = f1[i];
        __nv_bfloat16 h = __float2bfloat16(x);
        h1[i] = h;
        l1[i] = __float2bfloat16(x - __bfloat162float(h));
    }
    {
        float x = f2[i];
        __nv_bfloat16 h = __float2bfloat16(x);
        h2[i] = h;
        l2[i] = __float2bfloat16(x - __bfloat162float(h));
    }
}

// ---------------- scores via mma.sync bf16 (2-way split, 3 passes) ---------
// Triple-buffered smem pipeline: ONE sync per K-chunk, 2-chunk load-ahead.
__device__ __forceinline__ void mma16816(float* c, const uint32_t* a, const uint32_t* b)
{
    asm volatile(
        "mma.sync.aligned.m16n8k16.row.col.f32.bf16.bf16.f32 "
        "{%0,%1,%2,%3}, {%4,%5,%6,%7}, {%8,%9}, {%0,%1,%2,%3};"
        : "+f"(c[0]), "+f"(c[1]), "+f"(c[2]), "+f"(c[3])
        : "r"(a[0]), "r"(a[1]), "r"(a[2]), "r"(a[3]), "r"(b[0]), "r"(b[1]));
}

__global__ __launch_bounds__(256, 1)
void mma_scores(const __nv_bfloat16* __restrict__ Ah, const __nv_bfloat16* __restrict__ Al,
                const __nv_bfloat16* __restrict__ Bh, const __nv_bfloat16* __restrict__ Bl,
                float* __restrict__ C)
{
    __shared__ __nv_bfloat16 As[3][128][40];
    __shared__ __nv_bfloat16 Bs[3][128][40];

    const int bz = blockIdx.z;
    const int m0 = blockIdx.y * 128, n0 = blockIdx.x * 128;
    const size_t base = (size_t)bz * NQ * MD;
    const int tid = threadIdx.x, warp = tid >> 5, lane = tid & 31;
    const int wm = (warp >> 2) * 64, wn = (warp & 3) * 32;

    float acc[4][4][4];
#pragma unroll
    for (int mi = 0; mi < 4; mi++)
#pragma unroll
        for (int ni = 0; ni < 4; ni++)
#pragma unroll
            for (int q = 0; q < 4; q++) acc[mi][ni][q] = 0.f;

    const int lrow = tid >> 1;
    const int loff = (tid & 1) * 16;

    const __nv_bfloat16* Aps[3] = { Ah + base + (size_t)m0 * MD,
                                    Ah + base + (size_t)m0 * MD,
                                    Al + base + (size_t)m0 * MD };
    const __nv_bfloat16* Bps[3] = { Bh + base + (size_t)n0 * MD,
                                    Bl + base + (size_t)n0 * MD,
                                    Bh + base + (size_t)n0 * MD };

    // chunk c: p = c>>3, kk = (c&7)*32; 24 chunks total
#define LOADCH(CC, A0, A1, B0, B1) do { \
        int p = (CC) >> 3, kk = ((CC) & 7) * 32; \
        const uint4* ga = (const uint4*)(Aps[p] + (size_t)lrow * MD + kk + loff); \
        const uint4* gb = (const uint4*)(Bps[p] + (size_t)lrow * MD + kk + loff); \
        A0 = ga[0]; A1 = ga[1]; B0 = gb[0]; B1 = gb[1]; \
    } while (0)
#define STORECH(BUF, A0, A1, B0, B1) do { \
        *(uint4*)&As[BUF][lrow][loff]     = A0; \
        *(uint4*)&As[BUF][lrow][loff + 8] = A1; \
        *(uint4*)&Bs[BUF][lrow][loff]     = B0; \
        *(uint4*)&Bs[BUF][lrow][loff + 8] = B1; \
    } while (0)

    uint4 ra0, ra1, rb0, rb1;
    // prologue: fill buffers 0 and 1
    LOADCH(0, ra0, ra1, rb0, rb1);
    STORECH(0, ra0, ra1, rb0, rb1);
    LOADCH(1, ra0, ra1, rb0, rb1);
    STORECH(1, ra0, ra1, rb0, rb1);
    __syncthreads();

#pragma unroll 1
    for (int c = 0; c < 24; c++) {
        const int cur = c % 3;
        // store chunk c+2 into buf (c+2)%3 == (c-1)%3: its last reader was
        // compute at iter c-1, separated by iter c-1's sync (WAR safe);
        // its next reader is iter c+2, two syncs away (RAW safe).
        if (c + 2 < 24) {
            LOADCH(c + 2, ra0, ra1, rb0, rb1);
            STORECH((c + 2) % 3, ra0, ra1, rb0, rb1);
        }
#pragma unroll
        for (int ks = 0; ks < 32; ks += 16) {
            uint32_t afr[4][4], bfr[4][2];
            const int fr = lane >> 2, fc = ks + (lane & 3) * 2;
#pragma unroll
            for (int mi = 0; mi < 4; mi++) {
                int r = wm + mi * 16 + fr;
                afr[mi][0] = *(const uint32_t*)&As[cur][r][fc];
                afr[mi][1] = *(const uint32_t*)&As[cur][r + 8][fc];
                afr[mi][2] = *(const uint32_t*)&As[cur][r][fc + 8];
                afr[mi][3] = *(const uint32_t*)&As[cur][r + 8][fc + 8];
            }
#pragma unroll
            for (int ni = 0; ni < 4; ni++) {
                int r = wn + ni * 8 + fr;
                bfr[ni][0] = *(const uint32_t*)&Bs[cur][r][fc];
                bfr[ni][1] = *(const uint32_t*)&Bs[cur][r][fc + 8];
            }
#pragma unroll
            for (int mi = 0; mi < 4; mi++)
#pragma unroll
                for (int ni = 0; ni < 4; ni++)
                    mma16816(acc[mi][ni], afr[mi], bfr[ni]);
        }
        __syncthreads();
    }
#undef LOADCH
#undef STORECH

    float* Cb = C + (size_t)bz * NP * NP;
#pragma unroll
    for (int mi = 0; mi < 4; mi++) {
        int r0 = m0 + wm + mi * 16 + (lane >> 2);
#pragma unroll
        for (int ni = 0; ni < 4; ni++) {
            int c0 = n0 + wn + ni * 8 + (lane & 3) * 2;
            Cb[(size_t)r0 * NP + c0]           = acc[mi][ni][0] * 0.0625f;
            Cb[(size_t)r0 * NP + c0 + 1]       = acc[mi][ni][1] * 0.0625f;
            Cb[(size_t)(r0 + 8) * NP + c0]     = acc[mi][ni][2] * 0.0625f;
            Cb[(size_t)(r0 + 8) * NP + c0 + 1] = acc[mi][ni][3] * 0.0625f;
        }
    }
}

// -------- exp + dustbin + permute into mma A-fragment tiles ---------------
__global__ void expk_kernel(float* __restrict__ S, const float* __restrict__ bin,
                            uint4* __restrict__ Kp, uint4* __restrict__ KTp)
{
    __shared__ float tile[32][33];
    const int b  = blockIdx.z;
    const int i0 = blockIdx.y * 32, j0 = blockIdx.x * 32;
    const float alpha = *bin;
    float* Sb = S + (size_t)b * NP * NP;
    const int lane = threadIdx.x & 31;
    const int w = threadIdx.x >> 5;          // 0..7

#pragma unroll
    for (int q = 0; q < 4; q++) {
        int i = i0 + w + q * 8, j = j0 + lane;
        float e;
        if (i > 2048 || j > 2048) {
            e = 0.f;
        } else if (i == 2048 || j == 2048) {
            e = expf(alpha);
            Sb[(size_t)i * NP + j] = alpha;
        } else {
            e = expf(Sb[(size_t)i * NP + j]);
        }
        tile[w + q * 8][lane] = e;
    }
    __syncthreads();

    const int r0 = lane >> 2, c0 = (lane & 3) * 2;
    if (w < 4) {
        const int h_r = w >> 1, h_c = w & 1;
        const int rt = 2 * blockIdx.y + h_r, ct = 2 * blockIdx.x + h_c;
        if (rt < NT && ct < NT) {
            const int rr = h_r * 16 + r0, cc = h_c * 16 + c0;
            __half2 a0 = __floats2half2_rn(tile[rr][cc],         tile[rr][cc + 1]);
            __half2 a1 = __floats2half2_rn(tile[rr + 8][cc],     tile[rr + 8][cc + 1]);
            __half2 a2 = __floats2half2_rn(tile[rr][cc + 8],     tile[rr][cc + 9]);
            __half2 a3 = __floats2half2_rn(tile[rr + 8][cc + 8], tile[rr + 8][cc + 9]);
            uint4 v;
            v.x = *(uint32_t*)&a0; v.y = *(uint32_t*)&a1;
            v.z = *(uint32_t*)&a2; v.w = *(uint32_t*)&a3;
            Kp[(((size_t)b * NT + rt) * NT + ct) * 32 + lane] = v;
        }
    } else {
        const int wk = w - 4;
        const int h_r = wk >> 1, h_c = wk & 1;
        const int rt = 2 * blockIdx.x + h_r, ct = 2 * blockIdx.y + h_c;
        if (rt < NT && ct < NT) {
            const int cr = h_c * 16 + c0, rr = h_r * 16 + r0;
            __half2 a0 = __floats2half2_rn(tile[cr][rr],         tile[cr + 1][rr]);
            __half2 a1 = __floats2half2_rn(tile[cr][rr + 8],     tile[cr + 1][rr + 8]);
            __half2 a2 = __floats2half2_rn(tile[cr + 8][rr],     tile[cr + 9][rr]);
            __half2 a3 = __floats2half2_rn(tile[cr + 8][rr + 8], tile[cr + 9][rr + 8]);
            uint4 v;
            v.x = *(uint32_t*)&a0; v.y = *(uint32_t*)&a1;
            v.z = *(uint32_t*)&a2; v.w = *(uint32_t*)&a3;
            KTp[(((size_t)b * NT + rt) * NT + ct) * 32 + lane] = v;
        }
    }
}

// ---------------- barrier + convergence state reset (per graph replay) -----
__global__ void reset_bar()
{
    int i = threadIdx.x;
    if (i < NB * 32) {
        g_bar_cnt[i] = 0;
        g_bar_epoch[i] = 0;
    }
    if (i < NB * 128) g_conv[i] = 0;
}

// ---------------- per-batch barrier: 37 arrivals, own L2 line --------------
__device__ __forceinline__ void batch_barrier(int batch, unsigned k)
{
    __syncthreads();
    if (threadIdx.x == 0) {
        __threadfence();
        unsigned t = atomicAdd(&g_bar_cnt[batch * 32], 1u);
        if (t == (k + 1u) * SUBB - 1u) {
            atomicAdd(&g_bar_epoch[batch * 32], 1u);
        } else {
            while (*(volatile unsigned*)&g_bar_epoch[batch * 32] <= k) { }
        }
        __threadfence();
    }
    __syncthreads();
}

// ---------------- HMMA Sinkhorn half-pass (pipelined) ----------------------
// Per row-tile: front-batch ALL 4-5 tile LDG.128s (MLP=5), then MMAs.
// cflag != nullptr: set *cflag = 1 if any updated value moved > 3e-6 rel.
__device__ __forceinline__ void sink_half(const uint4* __restrict__ Kb,
                                          const float* __restrict__ x,
                                          float* __restrict__ y,
                                          int batch, int sub,
                                          uint32_t* xh, float (*sred)[16][33],
                                          int* cflag)
{
    const float* xb = x + batch * STR;
    for (int i = threadIdx.x; i < 1032; i += 1024) {
        int j = i * 2;
        float v0 = (j < NP) ? xb[j] : 0.f;
        float v1 = (j + 1 < NP) ? xb[j + 1] : 0.f;
        __half2 h = __floats2half2_rn(v0, v1);
        xh[i] = *(uint32_t*)&h;
    }
    __syncthreads();

    const int w = threadIdx.x >> 5, lane = threadIdx.x & 31;
    const int lm = lane & 3;
    const int r8 = lane >> 2;

#pragma unroll 1
    for (int rl = 0; rl < 4; rl++) {
        const int rt = sub + rl * SUBB;
        if (rt >= NT) break;
        const uint4* Kt = Kb + ((size_t)rt * NT) * 32 + lane;
        uint4 af0 = Kt[(size_t)(w      ) * 32];
        uint4 af1 = Kt[(size_t)(w +  32) * 32];
        uint4 af2 = Kt[(size_t)(w +  64) * 32];
        uint4 af3 = Kt[(size_t)(w +  96) * 32];
        uint4 af4;
        const bool has5 = (w == 0);
        if (has5) af4 = Kt[(size_t)128 * 32];

        float c0 = 0.f, c1 = 0.f, c2 = 0.f, c3 = 0.f;
        uint32_t b0, b1;
#define SINK_MMA(AF, CT) \
        b0 = xh[(CT) * 8 + lm]; b1 = xh[(CT) * 8 + 4 + lm]; \
        asm volatile( \
            "mma.sync.aligned.m16n8k16.row.col.f32.f16.f16.f32 " \
            "{%0,%1,%2,%3}, {%4,%5,%6,%7}, {%8,%9}, {%0,%1,%2,%3};" \
            : "+f"(c0), "+f"(c1), "+f"(c2), "+f"(c3) \
            : "r"((AF).x), "r"((AF).y), "r"((AF).z), "r"((AF).w), \
              "r"(b0), "r"(b1))
        SINK_MMA(af0, w);
        SINK_MMA(af1, w + 32);
        SINK_MMA(af2, w + 64);
        SINK_MMA(af3, w + 96);
        if (has5) { SINK_MMA(af4, 128); }
#undef SINK_MMA
        if (lm == 0) {
            sred[rl][r8][w]     = c0;
            sred[rl][r8 + 8][w] = c2;
        }
    }
    __syncthreads();
    if (threadIdx.x < 64) {
        const int rl = threadIdx.x >> 4, r = threadIdx.x & 15;
        const int rt = sub + rl * SUBB;
        if (rt < NT) {
            float s = 0.f;
#pragma unroll
            for (int q = 0; q < 32; q++) s += sred[rl][r][q];
            int row = rt * 16 + r;
            if (row < NP) {
                float mu = (row < NQ) ? 1.0f : 2048.0f;  // scaled mu' = 4096*mu
                float nv = mu / s;
                if (cflag) {
                    float old = y[batch * STR + row];
                    if (fabsf(nv - old) > 3e-6f * fabsf(old)) *cflag = 1;
                }
                y[batch * STR + row] = nv;
            }
        }
    }
    __syncthreads();
}

// ---------------- persistent Sinkhorn: <=100 iterations, early exit --------
__global__ __launch_bounds__(1024, 1)
void sink_persist(const uint4* __restrict__ Kp, const uint4* __restrict__ KTp,
                  float* __restrict__ a, float* __restrict__ bv)
{
    __shared__ __align__(16) uint32_t xh[1032];
    __shared__ float sred[4][16][33];
    const int bl = blockIdx.x;
    const int batch = bl / SUBB, sub = bl % SUBB;
    const uint4* Kb  = Kp  + (size_t)batch * NT * NT * 32;
    const uint4* KTb = KTp + (size_t)batch * NT * NT * 32;

    for (int i = threadIdx.x; i < NP; i += 1024) bv[batch * STR + i] = 1.0f;

    unsigned bk = 0;
    batch_barrier(batch, bk++);
    for (int it = 0; it < 100; it++) {
        sink_half(Kb, bv, a, batch, sub, xh, sred, nullptr);
        batch_barrier(batch, bk++);
        sink_half(KTb, a, bv, batch, sub, xh, sred,
                  &g_conv[batch * 128 + it]);
        batch_barrier(batch, bk++);
        // all blocks of this batch observe the same flag post-barrier
        if (*(volatile int*)&g_conv[batch * 128 + it] == 0) break;
    }
}

// ---------------- final: out = exp(S) * a'_i * b_j, in place ---------------
__global__ void final_kernel(float* __restrict__ out,
                             const float* __restrict__ a,
                             const float* __restrict__ bv)
{
    const int b = blockIdx.y;
    const int row = blockIdx.x;
    const float av = a[b * STR + row];
    float* o = out + (size_t)b * NP * NP + (size_t)row * NP;
    const float* bb = bv + b * STR;
    for (int j = threadIdx.x; j < NP; j += 256)
        o[j] = expf(o[j]) * av * bb[j];
}

// ---------------- launch ----------------
extern "C" void kernel_launch(void* const* d_in, const int* in_sizes, int n_in,
                              void* d_out, int out_size)
{
    const float* Xlc  = (const float*)d_in[0];
    const float* Xte  = (const float*)d_in[1];
    const float* W1lc = (const float*)d_in[2];
    const float* b1lc = (const float*)d_in[3];
    const float* W2lc = (const float*)d_in[4];
    const float* b2lc = (const float*)d_in[5];
    const float* W1te = (const float*)d_in[6];
    const float* b1te = (const float*)d_in[7];
    const float* W2te = (const float*)d_in[8];
    const float* b2te = (const float*)d_in[9];
    const float* bin  = (const float*)d_in[10];
    float* out = (float*)d_out;

    float *f1, *f2, *h1, *h2, *a, *bv;
    uint4 *Kp, *KTp;
    __nv_bfloat16 *s1h, *s1l, *s2h, *s2l;
    cudaGetSymbolAddress((void**)&f1, g_f1);
    cudaGetSymbolAddress((void**)&f2, g_f2);
    cudaGetSymbolAddress((void**)&h1, g_h1);
    cudaGetSymbolAddress((void**)&h2, g_h2);
    cudaGetSymbolAddress((void**)&a,  g_a);
    cudaGetSymbolAddress((void**)&bv, g_bv);
    cudaGetSymbolAddress((void**)&Kp, g_Kp);
    cudaGetSymbolAddress((void**)&KTp, g_KTp);
    cudaGetSymbolAddress((void**)&s1h, g_s1h);
    cudaGetSymbolAddress((void**)&s1l, g_s1l);
    cudaGetSymbolAddress((void**)&s2h, g_s2h);
    cudaGetSymbolAddress((void**)&s2l, g_s2l);

    // MLPs: layer1 (relu) for lc+te in one launch, then layer2
    dim3 gMLP(2, 64, 2);
    {
        MlpArgs a1;
        a1.A[0] = Xlc; a1.B[0] = W1lc; a1.bias[0] = b1lc; a1.C[0] = h1;
        a1.A[1] = Xte; a1.B[1] = W1te; a1.bias[1] = b1te; a1.C[1] = h2;
        sgemm_mlp<<<gMLP, 256>>>(a1, 1);
        MlpArgs a2;
        a2.A[0] = h1; a2.B[0] = W2lc; a2.bias[0] = b2lc; a2.C[0] = f1;
        a2.A[1] = h2; a2.B[1] = W2te; a2.bias[1] = b2te; a2.C[1] = f2;
        sgemm_mlp<<<gMLP, 256>>>(a2, 0);
    }

    // split f1/f2 into bf16 hi/lo
    split_bf16<<<(NB * NQ * MD) / 256, 256>>>(f1, f2, s1h, s1l, s2h, s2l);

    // scores via tensor cores: 3-pass split bf16, fp32 accum, into d_out
    mma_scores<<<dim3(16, 16, NB), 256>>>(s1h, s1l, s2h, s2l, out);

    // exp + dustbin + permute into fragment tiles (Kp, KTp)
    expk_kernel<<<dim3(65, 65, NB), 256>>>(out, bin, Kp, KTp);

    // Sinkhorn: persistent HMMA kernel, per-batch barriers, early exit
    reset_bar<<<1, 512>>>();
    sink_persist<<<NBLK, 1024>>>(Kp, KTp, a, bv);

    // out = exp(S) * a'_i * b_j
    final_kernel<<<dim3(NP, NB), 256>>>(out, a, bv);
}

// round 17
// speedup vs baseline: 1.0428x; 1.0428x over previous
#include <cuda_runtime.h>
#include <cuda_fp16.h>
#include <cuda_bf16.h>
#include <stdint.h>

// Problem constants
#define NB   4        // batches
#define NQ   2048     // N_LC = N_TE
#define NP   2049     // NQ + dustbin
#define MD   256      // feature dim D
#define STR  2064     // padded stride for a/b vectors
#define NT   129      // 16x16 tiles per dim (129*16 = 2064, zero-padded)

// Persistent sink config: 148 blocks, 37/batch
#define NBLK 148
#define SUBB 37

// ---------------- device scratch (static, no allocation) ----------------
// K in mma A-fragment layout: [batch][row-tile][col-tile][lane] = 16 bytes
static __device__ uint4 g_Kp [(size_t)NB * NT * NT * 32];   // exp(Z) tiles
static __device__ uint4 g_KTp[(size_t)NB * NT * NT * 32];   // exp(Z)^T tiles
static __device__ float  g_f1[(size_t)NB * NQ * MD];
static __device__ float  g_f2[(size_t)NB * NQ * MD];
static __device__ float  g_h1[(size_t)NB * NQ * MD];
static __device__ float  g_h2[(size_t)NB * NQ * MD];
static __device__ __nv_bfloat16 g_s1h[(size_t)NB * NQ * MD];
static __device__ __nv_bfloat16 g_s1l[(size_t)NB * NQ * MD];
static __device__ __nv_bfloat16 g_s2h[(size_t)NB * NQ * MD];
static __device__ __nv_bfloat16 g_s2l[(size_t)NB * NQ * MD];
static __device__ float  g_a [NB * STR];                // scaled a' = 4096*a
static __device__ float  g_bv[NB * STR];                // b
// per-batch barrier state, each counter/epoch on its own 128B line
static __device__ unsigned g_bar_cnt[NB * 32];
static __device__ unsigned g_bar_epoch[NB * 32];
// per-batch, per-iteration "not converged" flags
static __device__ int g_conv[NB * 128];

// ---------------- MLP GEMM: 2 pointer sets selected by blockIdx.z ----------
struct MlpArgs {
    const float* A[2];
    const float* B[2];
    const float* bias[2];
    float* C[2];
};

__global__ __launch_bounds__(256, 2)
void sgemm_mlp(MlpArgs args, int relu)
{
    __shared__ float As[8][128];
    __shared__ float Bs[8][128];
    const int z = blockIdx.z;
    const float* A = args.A[z];
    const float* B = args.B[z];
    const float* bias = args.bias[z];
    float* C = args.C[z];
    const int K = MD;

    const int tid = threadIdx.x;
    const int tx = tid & 15, ty = tid >> 4;
    const int brow = blockIdx.y << 7;
    const int bcol = blockIdx.x << 7;
    const int lr = tid >> 1;
    const int lk = (tid & 1) << 2;

    const float* Ald = A + (long long)(brow + lr) * K + lk;
    const float* Bld = B + (long long)(bcol + lr) * K + lk;

    float acc[8][8];
#pragma unroll
    for (int i = 0; i < 8; i++)
#pragma unroll
        for (int j = 0; j < 8; j++) acc[i][j] = 0.f;

    for (int kk = 0; kk < K; kk += 8) {
        float4 av = *(const float4*)(Ald + kk);
        float4 bv = *(const float4*)(Bld + kk);
        __syncthreads();
        As[lk + 0][lr] = av.x; As[lk + 1][lr] = av.y;
        As[lk + 2][lr] = av.z; As[lk + 3][lr] = av.w;
        Bs[lk + 0][lr] = bv.x; Bs[lk + 1][lr] = bv.y;
        Bs[lk + 2][lr] = bv.z; Bs[lk + 3][lr] = bv.w;
        __syncthreads();
#pragma unroll
        for (int k = 0; k < 8; k++) {
            float ar[8], br[8];
            *(float4*)&ar[0] = *(const float4*)&As[k][ty * 4];
            *(float4*)&ar[4] = *(const float4*)&As[k][ty * 4 + 64];
            *(float4*)&br[0] = *(const float4*)&Bs[k][tx * 4];
            *(float4*)&br[4] = *(const float4*)&Bs[k][tx * 4 + 64];
#pragma unroll
            for (int i = 0; i < 8; i++)
#pragma unroll
                for (int j = 0; j < 8; j++)
                    acc[i][j] = fmaf(ar[i], br[j], acc[i][j]);
        }
    }

#pragma unroll
    for (int i = 0; i < 8; i++) {
        int row = brow + ty * 4 + ((i < 4) ? i : 60 + i);
#pragma unroll
        for (int j = 0; j < 8; j++) {
            int col = bcol + tx * 4 + ((j < 4) ? j : 60 + j);
            float v = acc[i][j] + bias[col];
            if (relu) v = fmaxf(v, 0.f);
            C[(long long)row * MD + col] = v;
        }
    }
}

// ---------------- split fp32 -> bf16 hi + lo ----------------
__global__ void split_bf16(const float* __restrict__ f1, const float* __restrict__ f2,
                           __nv_bfloat16* __restrict__ h1, __nv_bfloat16* __restrict__ l1,
                           __nv_bfloat16* __restrict__ h2, __nv_bfloat16* __restrict__ l2)
{
    int i = blockIdx.x * 256 + threadIdx.x;
    {
        float x = f1[i];
        __nv_bfloat16 h = __float2bfloat16(x);
        h1[i] = h;
        l1[i] = __float2bfloat16(x - __bfloat162float(h));
    }
    {
        float x = f2[i];
        __nv_bfloat16 h = __float2bfloat16(x);
        h2[i] = h;
        l2[i] = __float2bfloat16(x - __bfloat162float(h));
    }
}

// ---------------- scores via mma.sync bf16 (2-way split, 3 passes) ---------
// Double-buffered smem (R15 measured-good): next chunk's loads before compute.
__device__ __forceinline__ void mma16816(float* c, const uint32_t* a, const uint32_t* b)
{
    asm volatile(
        "mma.sync.aligned.m16n8k16.row.col.f32.bf16.bf16.f32 "
        "{%0,%1,%2,%3}, {%4,%5,%6,%7}, {%8,%9}, {%0,%1,%2,%3};"
        : "+f"(c[0]), "+f"(c[1]), "+f"(c[2]), "+f"(c[3])
        : "r"(a[0]), "r"(a[1]), "r"(a[2]), "r"(a[3]), "r"(b[0]), "r"(b[1]));
}

__global__ __launch_bounds__(256, 1)
void mma_scores(const __nv_bfloat16* __restrict__ Ah, const __nv_bfloat16* __restrict__ Al,
                const __nv_bfloat16* __restrict__ Bh, const __nv_bfloat16* __restrict__ Bl,
                float* __restrict__ C)
{
    __shared__ __nv_bfloat16 As[2][128][40];
    __shared__ __nv_bfloat16 Bs[2][128][40];

    const int bz = blockIdx.z;
    const int m0 = blockIdx.y * 128, n0 = blockIdx.x * 128;
    const size_t base = (size_t)bz * NQ * MD;
    const int tid = threadIdx.x, warp = tid >> 5, lane = tid & 31;
    const int wm = (warp >> 2) * 64, wn = (warp & 3) * 32;

    float acc[4][4][4];
#pragma unroll
    for (int mi = 0; mi < 4; mi++)
#pragma unroll
        for (int ni = 0; ni < 4; ni++)
#pragma unroll
            for (int q = 0; q < 4; q++) acc[mi][ni][q] = 0.f;

    const int lrow = tid >> 1;
    const int loff = (tid & 1) * 16;

    const __nv_bfloat16* Aps[3] = { Ah + base + (size_t)m0 * MD,
                                    Ah + base + (size_t)m0 * MD,
                                    Al + base + (size_t)m0 * MD };
    const __nv_bfloat16* Bps[3] = { Bh + base + (size_t)n0 * MD,
                                    Bl + base + (size_t)n0 * MD,
                                    Bh + base + (size_t)n0 * MD };

    uint4 ra0, ra1, rb0, rb1;
    // chunk c: p = c>>3, kk = (c&7)*32; 24 chunks total
    {
        const uint4* ga = (const uint4*)(Aps[0] + (size_t)lrow * MD + loff);
        const uint4* gb = (const uint4*)(Bps[0] + (size_t)lrow * MD + loff);
        ra0 = ga[0]; ra1 = ga[1];
        rb0 = gb[0]; rb1 = gb[1];
    }
    *(uint4*)&As[0][lrow][loff]     = ra0;
    *(uint4*)&As[0][lrow][loff + 8] = ra1;
    *(uint4*)&Bs[0][lrow][loff]     = rb0;
    *(uint4*)&Bs[0][lrow][loff + 8] = rb1;
    __syncthreads();

#pragma unroll 1
    for (int c = 0; c < 24; c++) {
        const int cur = c & 1;
        if (c + 1 < 24) {
            int p = (c + 1) >> 3, kk = ((c + 1) & 7) * 32;
            const uint4* ga = (const uint4*)(Aps[p] + (size_t)lrow * MD + kk + loff);
            const uint4* gb = (const uint4*)(Bps[p] + (size_t)lrow * MD + kk + loff);
            ra0 = ga[0]; ra1 = ga[1];
            rb0 = gb[0]; rb1 = gb[1];
        }
#pragma unroll
        for (int ks = 0; ks < 32; ks += 16) {
            uint32_t afr[4][4], bfr[4][2];
            const int fr = lane >> 2, fc = ks + (lane & 3) * 2;
#pragma unroll
            for (int mi = 0; mi < 4; mi++) {
                int r = wm + mi * 16 + fr;
                afr[mi][0] = *(const uint32_t*)&As[cur][r][fc];
                afr[mi][1] = *(const uint32_t*)&As[cur][r + 8][fc];
                afr[mi][2] = *(const uint32_t*)&As[cur][r][fc + 8];
                afr[mi][3] = *(const uint32_t*)&As[cur][r + 8][fc + 8];
            }
#pragma unroll
            for (int ni = 0; ni < 4; ni++) {
                int r = wn + ni * 8 + fr;
                bfr[ni][0] = *(const uint32_t*)&Bs[cur][r][fc];
                bfr[ni][1] = *(const uint32_t*)&Bs[cur][r][fc + 8];
            }
#pragma unroll
            for (int mi = 0; mi < 4; mi++)
#pragma unroll
                for (int ni = 0; ni < 4; ni++)
                    mma16816(acc[mi][ni], afr[mi], bfr[ni]);
        }
        if (c + 1 < 24) {
            const int nxt = (c + 1) & 1;
            __syncthreads();
            *(uint4*)&As[nxt][lrow][loff]     = ra0;
            *(uint4*)&As[nxt][lrow][loff + 8] = ra1;
            *(uint4*)&Bs[nxt][lrow][loff]     = rb0;
            *(uint4*)&Bs[nxt][lrow][loff + 8] = rb1;
            __syncthreads();
        }
    }

    float* Cb = C + (size_t)bz * NP * NP;
#pragma unroll
    for (int mi = 0; mi < 4; mi++) {
        int r0 = m0 + wm + mi * 16 + (lane >> 2);
#pragma unroll
        for (int ni = 0; ni < 4; ni++) {
            int c0 = n0 + wn + ni * 8 + (lane & 3) * 2;
            Cb[(size_t)r0 * NP + c0]           = acc[mi][ni][0] * 0.0625f;
            Cb[(size_t)r0 * NP + c0 + 1]       = acc[mi][ni][1] * 0.0625f;
            Cb[(size_t)(r0 + 8) * NP + c0]     = acc[mi][ni][2] * 0.0625f;
            Cb[(size_t)(r0 + 8) * NP + c0 + 1] = acc[mi][ni][3] * 0.0625f;
        }
    }
}

// -------- exp + dustbin + permute into mma A-fragment tiles ---------------
// __expf: MUFU.EX2 fast path; rel err ~1e-6, far below fp16-K noise.
__global__ void expk_kernel(float* __restrict__ S, const float* __restrict__ bin,
                            uint4* __restrict__ Kp, uint4* __restrict__ KTp)
{
    __shared__ float tile[32][33];
    const int b  = blockIdx.z;
    const int i0 = blockIdx.y * 32, j0 = blockIdx.x * 32;
    const float alpha = *bin;
    float* Sb = S + (size_t)b * NP * NP;
    const int lane = threadIdx.x & 31;
    const int w = threadIdx.x >> 5;          // 0..7

#pragma unroll
    for (int q = 0; q < 4; q++) {
        int i = i0 + w + q * 8, j = j0 + lane;
        float e;
        if (i > 2048 || j > 2048) {
            e = 0.f;
        } else if (i == 2048 || j == 2048) {
            e = __expf(alpha);
            Sb[(size_t)i * NP + j] = alpha;
        } else {
            e = __expf(Sb[(size_t)i * NP + j]);
        }
        tile[w + q * 8][lane] = e;
    }
    __syncthreads();

    const int r0 = lane >> 2, c0 = (lane & 3) * 2;
    if (w < 4) {
        const int h_r = w >> 1, h_c = w & 1;
        const int rt = 2 * blockIdx.y + h_r, ct = 2 * blockIdx.x + h_c;
        if (rt < NT && ct < NT) {
            const int rr = h_r * 16 + r0, cc = h_c * 16 + c0;
            __half2 a0 = __floats2half2_rn(tile[rr][cc],         tile[rr][cc + 1]);
            __half2 a1 = __floats2half2_rn(tile[rr + 8][cc],     tile[rr + 8][cc + 1]);
            __half2 a2 = __floats2half2_rn(tile[rr][cc + 8],     tile[rr][cc + 9]);
            __half2 a3 = __floats2half2_rn(tile[rr + 8][cc + 8], tile[rr + 8][cc + 9]);
            uint4 v;
            v.x = *(uint32_t*)&a0; v.y = *(uint32_t*)&a1;
            v.z = *(uint32_t*)&a2; v.w = *(uint32_t*)&a3;
            Kp[(((size_t)b * NT + rt) * NT + ct) * 32 + lane] = v;
        }
    } else {
        const int wk = w - 4;
        const int h_r = wk >> 1, h_c = wk & 1;
        const int rt = 2 * blockIdx.x + h_r, ct = 2 * blockIdx.y + h_c;
        if (rt < NT && ct < NT) {
            const int cr = h_c * 16 + c0, rr = h_r * 16 + r0;
            __half2 a0 = __floats2half2_rn(tile[cr][rr],         tile[cr + 1][rr]);
            __half2 a1 = __floats2half2_rn(tile[cr][rr + 8],     tile[cr + 1][rr + 8]);
            __half2 a2 = __floats2half2_rn(tile[cr + 8][rr],     tile[cr + 9][rr]);
            __half2 a3 = __floats2half2_rn(tile[cr + 8][rr + 8], tile[cr + 9][rr + 8]);
            uint4 v;
            v.x = *(uint32_t*)&a0; v.y = *(uint32_t*)&a1;
            v.z = *(uint32_t*)&a2; v.w = *(uint32_t*)&a3;
            KTp[(((size_t)b * NT + rt) * NT + ct) * 32 + lane] = v;
        }
    }
}

// ---------------- barrier + convergence state reset (per graph replay) -----
__global__ void reset_bar()
{
    int i = threadIdx.x;
    if (i < NB * 32) {
        g_bar_cnt[i] = 0;
        g_bar_epoch[i] = 0;
    }
    if (i < NB * 128) g_conv[i] = 0;
}

// ---------------- per-batch barrier: 37 arrivals, own L2 line --------------
__device__ __forceinline__ void batch_barrier(int batch, unsigned k)
{
    __syncthreads();
    if (threadIdx.x == 0) {
        __threadfence();
        unsigned t = atomicAdd(&g_bar_cnt[batch * 32], 1u);
        if (t == (k + 1u) * SUBB - 1u) {
            atomicAdd(&g_bar_epoch[batch * 32], 1u);
        } else {
            while (*(volatile unsigned*)&g_bar_epoch[batch * 32] <= k) { }
        }
        __threadfence();
    }
    __syncthreads();
}

// ---------------- HMMA Sinkhorn half-pass (pipelined) ----------------------
// Per row-tile: front-batch ALL 4-5 tile LDG.128s (MLP=5), then MMAs.
// cflag != nullptr: set *cflag = 1 if any updated value moved > 3e-6 rel.
__device__ __forceinline__ void sink_half(const uint4* __restrict__ Kb,
                                          const float* __restrict__ x,
                                          float* __restrict__ y,
                                          int batch, int sub,
                                          uint32_t* xh, float (*sred)[16][33],
                                          int* cflag)
{
    const float* xb = x + batch * STR;
    for (int i = threadIdx.x; i < 1032; i += 1024) {
        int j = i * 2;
        float v0 = (j < NP) ? xb[j] : 0.f;
        float v1 = (j + 1 < NP) ? xb[j + 1] : 0.f;
        __half2 h = __floats2half2_rn(v0, v1);
        xh[i] = *(uint32_t*)&h;
    }
    __syncthreads();

    const int w = threadIdx.x >> 5, lane = threadIdx.x & 31;
    const int lm = lane & 3;
    const int r8 = lane >> 2;

#pragma unroll 1
    for (int rl = 0; rl < 4; rl++) {
        const int rt = sub + rl * SUBB;
        if (rt >= NT) break;
        const uint4* Kt = Kb + ((size_t)rt * NT) * 32 + lane;
        uint4 af0 = Kt[(size_t)(w      ) * 32];
        uint4 af1 = Kt[(size_t)(w +  32) * 32];
        uint4 af2 = Kt[(size_t)(w +  64) * 32];
        uint4 af3 = Kt[(size_t)(w +  96) * 32];
        uint4 af4;
        const bool has5 = (w == 0);
        if (has5) af4 = Kt[(size_t)128 * 32];

        float c0 = 0.f, c1 = 0.f, c2 = 0.f, c3 = 0.f;
        uint32_t b0, b1;
#define SINK_MMA(AF, CT) \
        b0 = xh[(CT) * 8 + lm]; b1 = xh[(CT) * 8 + 4 + lm]; \
        asm volatile( \
            "mma.sync.aligned.m16n8k16.row.col.f32.f16.f16.f32 " \
            "{%0,%1,%2,%3}, {%4,%5,%6,%7}, {%8,%9}, {%0,%1,%2,%3};" \
            : "+f"(c0), "+f"(c1), "+f"(c2), "+f"(c3) \
            : "r"((AF).x), "r"((AF).y), "r"((AF).z), "r"((AF).w), \
              "r"(b0), "r"(b1))
        SINK_MMA(af0, w);
        SINK_MMA(af1, w + 32);
        SINK_MMA(af2, w + 64);
        SINK_MMA(af3, w + 96);
        if (has5) { SINK_MMA(af4, 128); }
#undef SINK_MMA
        if (lm == 0) {
            sred[rl][r8][w]     = c0;
            sred[rl][r8 + 8][w] = c2;
        }
    }
    __syncthreads();
    if (threadIdx.x < 64) {
        const int rl = threadIdx.x >> 4, r = threadIdx.x & 15;
        const int rt = sub + rl * SUBB;
        if (rt < NT) {
            float s = 0.f;
#pragma unroll
            for (int q = 0; q < 32; q++) s += sred[rl][r][q];
            int row = rt * 16 + r;
            if (row < NP) {
                float mu = (row < NQ) ? 1.0f : 2048.0f;  // scaled mu' = 4096*mu
                float nv = mu / s;
                if (cflag) {
                    float old = y[batch * STR + row];
                    if (fabsf(nv - old) > 3e-6f * fabsf(old)) *cflag = 1;
                }
                y[batch * STR + row] = nv;
            }
        }
    }
    __syncthreads();
}

// ---------------- persistent Sinkhorn: <=100 iterations, early exit --------
__global__ __launch_bounds__(1024, 1)
void sink_persist(const uint4* __restrict__ Kp, const uint4* __restrict__ KTp,
                  float* __restrict__ a, float* __restrict__ bv)
{
    __shared__ __align__(16) uint32_t xh[1032];
    __shared__ float sred[4][16][33];
    const int bl = blockIdx.x;
    const int batch = bl / SUBB, sub = bl % SUBB;
    const uint4* Kb  = Kp  + (size_t)batch * NT * NT * 32;
    const uint4* KTb = KTp + (size_t)batch * NT * NT * 32;

    for (int i = threadIdx.x; i < NP; i += 1024) bv[batch * STR + i] = 1.0f;

    unsigned bk = 0;
    batch_barrier(batch, bk++);
    for (int it = 0; it < 100; it++) {
        sink_half(Kb, bv, a, batch, sub, xh, sred, nullptr);
        batch_barrier(batch, bk++);
        sink_half(KTb, a, bv, batch, sub, xh, sred,
                  &g_conv[batch * 128 + it]);
        batch_barrier(batch, bk++);
        // all blocks of this batch observe the same flag post-barrier
        if (*(volatile int*)&g_conv[batch * 128 + it] == 0) break;
    }
}

// ---------------- final: out = exp(S) * a'_i * b_j, in place ---------------
__global__ void final_kernel(float* __restrict__ out,
                             const float* __restrict__ a,
                             const float* __restrict__ bv)
{
    const int b = blockIdx.y;
    const int row = blockIdx.x;
    const float av = a[b * STR + row];
    float* o = out + (size_t)b * NP * NP + (size_t)row * NP;
    const float* bb = bv + b * STR;
    for (int j = threadIdx.x; j < NP; j += 256)
        o[j] = __expf(o[j]) * av * bb[j];
}

// ---------------- launch ----------------
extern "C" void kernel_launch(void* const* d_in, const int* in_sizes, int n_in,
                              void* d_out, int out_size)
{
    const float* Xlc  = (const float*)d_in[0];
    const float* Xte  = (const float*)d_in[1];
    const float* W1lc = (const float*)d_in[2];
    const float* b1lc = (const float*)d_in[3];
    const float* W2lc = (const float*)d_in[4];
    const float* b2lc = (const float*)d_in[5];
    const float* W1te = (const float*)d_in[6];
    const float* b1te = (const float*)d_in[7];
    const float* W2te = (const float*)d_in[8];
    const float* b2te = (const float*)d_in[9];
    const float* bin  = (const float*)d_in[10];
    float* out = (float*)d_out;

    float *f1, *f2, *h1, *h2, *a, *bv;
    uint4 *Kp, *KTp;
    __nv_bfloat16 *s1h, *s1l, *s2h, *s2l;
    cudaGetSymbolAddress((void**)&f1, g_f1);
    cudaGetSymbolAddress((void**)&f2, g_f2);
    cudaGetSymbolAddress((void**)&h1, g_h1);
    cudaGetSymbolAddress((void**)&h2, g_h2);
    cudaGetSymbolAddress((void**)&a,  g_a);
    cudaGetSymbolAddress((void**)&bv, g_bv);
    cudaGetSymbolAddress((void**)&Kp, g_Kp);
    cudaGetSymbolAddress((void**)&KTp, g_KTp);
    cudaGetSymbolAddress((void**)&s1h, g_s1h);
    cudaGetSymbolAddress((void**)&s1l, g_s1l);
    cudaGetSymbolAddress((void**)&s2h, g_s2h);
    cudaGetSymbolAddress((void**)&s2l, g_s2l);

    // MLPs: layer1 (relu) for lc+te in one launch, then layer2
    dim3 gMLP(2, 64, 2);
    {
        MlpArgs a1;
        a1.A[0] = Xlc; a1.B[0] = W1lc; a1.bias[0] = b1lc; a1.C[0] = h1;
        a1.A[1] = Xte; a1.B[1] = W1te; a1.bias[1] = b1te; a1.C[1] = h2;
        sgemm_mlp<<<gMLP, 256>>>(a1, 1);
        MlpArgs a2;
        a2.A[0] = h1; a2.B[0] = W2lc; a2.bias[0] = b2lc; a2.C[0] = f1;
        a2.A[1] = h2; a2.B[1] = W2te; a2.bias[1] = b2te; a2.C[1] = f2;
        sgemm_mlp<<<gMLP, 256>>>(a2, 0);
    }

    // split f1/f2 into bf16 hi/lo
    split_bf16<<<(NB * NQ * MD) / 256, 256>>>(f1, f2, s1h, s1l, s2h, s2l);

    // scores via tensor cores: 3-pass split bf16, fp32 accum, into d_out
    mma_scores<<<dim3(16, 16, NB), 256>>>(s1h, s1l, s2h, s2l, out);

    // exp + dustbin + permute into fragment tiles (Kp, KTp)
    expk_kernel<<<dim3(65, 65, NB), 256>>>(out, bin, Kp, KTp);

    // Sinkhorn: persistent HMMA kernel, per-batch barriers, early exit
    reset_bar<<<1, 512>>>();
    sink_persist<<<NBLK, 1024>>>(Kp, KTp, a, bv);

    // out = exp(S) * a'_i * b_j
    final_kernel<<<dim3(NP, NB), 256>>>(out, a, bv);
}